// round 1
// baseline (speedup 1.0000x reference)
#include <cuda_runtime.h>
#include <math.h>

// BN eval constant: 1/sqrt(1 + 1e-5)
#define BN_INV 0.9999950000374997f

// Scratch between stages (allocation-free rule -> __device__ globals)
__device__ float g_h1[2048 * 32 * 12 * 12];  // stage1 out [B,32,12,12]
__device__ float g_h2[2048 * 1024];          // stage2 out [B,1024]

// ---------------------------------------------------------------------------
// Block-wide sum reduction (256 threads). 3 syncthreads; safe for reuse.
// ---------------------------------------------------------------------------
__device__ __forceinline__ float blockReduceSum(float v, volatile float* sred, int tid) {
#pragma unroll
    for (int o = 16; o > 0; o >>= 1) v += __shfl_xor_sync(0xffffffffu, v, o);
    if ((tid & 31) == 0) sred[tid >> 5] = v;
    __syncthreads();
    if (tid < 32) {
        float x = (tid < 8) ? sred[tid] : 0.f;
#pragma unroll
        for (int o = 16; o > 0; o >>= 1) x += __shfl_xor_sync(0xffffffffu, x, o);
        if (tid == 0) sred[0] = x;
    }
    __syncthreads();
    float total = sred[0];
    __syncthreads();
    return total;
}

// ---------------------------------------------------------------------------
// Kernel 1: conv1(1->32, 5x5, 28->24) + per-sample ternarize + BN + maxpool2
//           + relu  -> g_h1 [B,32,12,12]
// One CTA per sample, 256 threads. Conv output (18432 f32) kept in smem.
// ---------------------------------------------------------------------------
__global__ __launch_bounds__(256) void k_conv1(
    const float* __restrict__ x, const float* __restrict__ w,
    const float* __restrict__ bconv, const float* __restrict__ bng,
    const float* __restrict__ bnb) {
    extern __shared__ float sm[];
    float* s_in   = sm;          // 28 rows * 29 (pad) = 812
    float* s_w    = sm + 812;    // 32*25 = 800
    float* s_b    = sm + 1612;   // 32
    float* s_conv = sm + 1644;   // 32*24*24 = 18432
    __shared__ float sred[32];

    const int n = blockIdx.x;
    const int tid = threadIdx.x;

    const float* xin = x + n * 784;
    for (int i = tid; i < 784; i += 256) {
        int r = i / 28, c = i - r * 28;
        s_in[r * 29 + c] = xin[i];
    }
    for (int i = tid; i < 800; i += 256) s_w[i] = w[i];
    if (tid < 32) s_b[tid] = bconv[tid];
    __syncthreads();

    // Conv: thread handles 3 (oc,oy) rows of 24 outputs; input row in regs.
    float labs = 0.f;
#pragma unroll
    for (int p = 0; p < 3; p++) {
        int pair = tid + p * 256;          // 0..767 = 32 oc * 24 oy
        int oc = pair / 24, oy = pair - oc * 24;
        float acc[24];
        float bias = s_b[oc];
#pragma unroll
        for (int ox = 0; ox < 24; ox++) acc[ox] = bias;
#pragma unroll
        for (int kh = 0; kh < 5; kh++) {
            float row[28];
            const float* rp = s_in + (oy + kh) * 29;
#pragma unroll
            for (int j = 0; j < 28; j++) row[j] = rp[j];
            const float* wp = s_w + oc * 25 + kh * 5;
#pragma unroll
            for (int kw = 0; kw < 5; kw++) {
                float wv = wp[kw];
#pragma unroll
                for (int ox = 0; ox < 24; ox++) acc[ox] += wv * row[ox + kw];
            }
        }
        float* cp = s_conv + oc * 576 + oy * 24;
#pragma unroll
        for (int ox = 0; ox < 24; ox++) {
            cp[ox] = acc[ox];
            labs += fabsf(acc[ox]);
        }
    }

    // Ternarize params over the 18432-elem sample
    float total = blockReduceSum(labs, sred, tid);
    float delta = 0.7f * total / 18432.0f;

    float msum = 0.f, cnt = 0.f;
    for (int i = tid; i < 18432; i += 256) {
        float a = fabsf(s_conv[i]);
        if (a > delta) { msum += a; cnt += 1.f; }
    }
    msum = blockReduceSum(msum, sred, tid);
    cnt  = blockReduceSum(cnt, sred, tid);
    float alpha = msum / cnt;

    // tern -> BN -> maxpool2 -> relu
    float* outp = g_h1 + n * 4608;
    for (int p = tid; p < 4608; p += 256) {
        int c = p / 144;
        int r = p - c * 144;
        int py = r / 12, px = r - py * 12;
        float sc = bng[c] * BN_INV, sh = bnb[c];
        const float* base = s_conv + c * 576 + (py * 2) * 24 + px * 2;
        float m = -1e30f;
#pragma unroll
        for (int dy = 0; dy < 2; dy++)
#pragma unroll
            for (int dx = 0; dx < 2; dx++) {
                float v = base[dy * 24 + dx];
                float t = (v > delta) ? alpha : ((v < -delta) ? -alpha : 0.f);
                float bnv = t * sc + sh;
                m = fmaxf(m, bnv);
            }
        outp[p] = fmaxf(m, 0.f);
    }
}

// ---------------------------------------------------------------------------
// Kernel 2: conv2(32->64, 5x5, 12->8) + tern + BN + maxpool2 + relu
//           -> g_h2 [B,1024]
// One CTA per sample. Thread = (oc, row-pair): 16 outputs, input row in regs.
// ---------------------------------------------------------------------------
__global__ __launch_bounds__(256) void k_conv2(
    const float* __restrict__ w, const float* __restrict__ bconv,
    const float* __restrict__ bng, const float* __restrict__ bnb) {
    __shared__ float s_in[4608];    // 32*12*12
    __shared__ float s_conv[4096];  // 64*8*8
    __shared__ float sred[32];

    const int n = blockIdx.x;
    const int tid = threadIdx.x;
    const float* xin = g_h1 + n * 4608;
    for (int i = tid; i < 4608; i += 256) s_in[i] = xin[i];
    __syncthreads();

    const int oc = tid >> 2;      // 0..63
    const int q  = tid & 3;       // 0..3
    const int y0 = q * 2;         // output rows y0, y0+1

    float acc[2][8];
    {
        float bias = bconv[oc];
#pragma unroll
        for (int a = 0; a < 2; a++)
#pragma unroll
            for (int b = 0; b < 8; b++) acc[a][b] = bias;
    }

    for (int ic = 0; ic < 32; ic++) {
        const float* wb = w + (oc * 32 + ic) * 25;
        float wv[25];
#pragma unroll
        for (int i = 0; i < 25; i++) wv[i] = __ldg(wb + i);
        const float* ib = s_in + ic * 144;
#pragma unroll
        for (int rr = 0; rr < 6; rr++) {
            float row[12];
            const float* rp = ib + (y0 + rr) * 12;
#pragma unroll
            for (int j = 0; j < 12; j++) row[j] = rp[j];
            if (rr < 5) {  // output row y0, kh = rr
#pragma unroll
                for (int kw = 0; kw < 5; kw++) {
                    float wvv = wv[rr * 5 + kw];
#pragma unroll
                    for (int ox = 0; ox < 8; ox++) acc[0][ox] += wvv * row[ox + kw];
                }
            }
            if (rr >= 1) {  // output row y0+1, kh = rr-1
#pragma unroll
                for (int kw = 0; kw < 5; kw++) {
                    float wvv = wv[(rr - 1) * 5 + kw];
#pragma unroll
                    for (int ox = 0; ox < 8; ox++) acc[1][ox] += wvv * row[ox + kw];
                }
            }
        }
    }

    float labs = 0.f;
#pragma unroll
    for (int oy2 = 0; oy2 < 2; oy2++)
#pragma unroll
        for (int ox = 0; ox < 8; ox++) {
            float v = acc[oy2][ox];
            s_conv[oc * 64 + (y0 + oy2) * 8 + ox] = v;
            labs += fabsf(v);
        }

    float total = blockReduceSum(labs, sred, tid);
    float delta = 0.7f * total / 4096.0f;

    float msum = 0.f, cnt = 0.f;
#pragma unroll
    for (int oy2 = 0; oy2 < 2; oy2++)
#pragma unroll
        for (int ox = 0; ox < 8; ox++) {
            float a = fabsf(acc[oy2][ox]);
            if (a > delta) { msum += a; cnt += 1.f; }
        }
    msum = blockReduceSum(msum, sred, tid);
    cnt  = blockReduceSum(cnt, sred, tid);
    float alpha = msum / cnt;

    // tern -> BN -> maxpool2 -> relu : 64*4*4 = 1024 outputs
    float* outp = g_h2 + n * 1024;
    for (int p = tid; p < 1024; p += 256) {
        int c = p >> 4;
        int r = p & 15;
        int py = r >> 2, px = r & 3;
        float sc = bng[c] * BN_INV, sh = bnb[c];
        const float* base = s_conv + c * 64 + (py * 2) * 8 + px * 2;
        float m = -1e30f;
#pragma unroll
        for (int dy = 0; dy < 2; dy++)
#pragma unroll
            for (int dx = 0; dx < 2; dx++) {
                float v = base[dy * 8 + dx];
                float t = (v > delta) ? alpha : ((v < -delta) ? -alpha : 0.f);
                float bnv = t * sc + sh;
                m = fmaxf(m, bnv);
            }
        outp[p] = fmaxf(m, 0.f);
    }
}

// ---------------------------------------------------------------------------
// Kernel 3: fc1 (1024->512) + tern + relu + fc2 (512->10) + tern -> out
// One CTA per 16 samples (weight reuse x16). W1 tiled through smem with
// conflict-free padded strides; x reads are pure broadcast -> FMA-bound.
// ---------------------------------------------------------------------------
#define SWT 529   // s_wt row stride (17*k + oc mod 32 bijective -> conflict-free)
#define SH  516   // s_h per-sample stride
#define SW2 529   // s_w2 row stride

__global__ __launch_bounds__(256) void k_fc(
    const float* __restrict__ w1, const float* __restrict__ b1,
    const float* __restrict__ w2, const float* __restrict__ b2,
    float* __restrict__ out) {
    extern __shared__ float sm[];
    float* s_x  = sm;                         // 16*1024 = 16384
    float* s_wt = sm + 16384;                 // 16*SWT  = 8464
    float* s_h  = sm + 16384 + 8464;          // 16*SH   = 8256
    float* s_w2 = sm + 16384 + 8464 + 8256;   // 10*SW2  = 5290
    float* s_o  = s_w2 + 5290;                // 160
    float* s_ad = s_o + 160;                  // 32 (delta[16], alpha[16])

    const int tid = threadIdx.x;
    const int n0 = blockIdx.x * 16;

    for (int i = tid; i < 16384; i += 256) s_x[i] = g_h2[n0 * 1024 + i];
    for (int i = tid; i < 5120; i += 256) {
        int oc = i >> 9, k = i & 511;
        s_w2[oc * SW2 + k] = w2[i];
    }
    __syncthreads();

    const int oc0 = tid, oc1 = tid + 256;
    float acc0[16], acc1[16];
    {
        float bb0 = b1[oc0], bb1 = b1[oc1];
#pragma unroll
        for (int s = 0; s < 16; s++) { acc0[s] = bb0; acc1[s] = bb1; }
    }

    for (int kt = 0; kt < 1024; kt += 16) {
        __syncthreads();
        for (int i = tid; i < 8192; i += 256) {
            int oc = i >> 4, kk = i & 15;
            s_wt[kk * SWT + oc] = w1[oc * 1024 + kt + kk];
        }
        __syncthreads();
#pragma unroll
        for (int kk = 0; kk < 16; kk += 4) {
            float w00 = s_wt[(kk + 0) * SWT + oc0];
            float w01 = s_wt[(kk + 1) * SWT + oc0];
            float w02 = s_wt[(kk + 2) * SWT + oc0];
            float w03 = s_wt[(kk + 3) * SWT + oc0];
            float w10 = s_wt[(kk + 0) * SWT + oc1];
            float w11 = s_wt[(kk + 1) * SWT + oc1];
            float w12 = s_wt[(kk + 2) * SWT + oc1];
            float w13 = s_wt[(kk + 3) * SWT + oc1];
#pragma unroll
            for (int s = 0; s < 16; s++) {
                const float4 xv =
                    *reinterpret_cast<const float4*>(&s_x[s * 1024 + kt + kk]);
                acc0[s] += w00 * xv.x + w01 * xv.y + w02 * xv.z + w03 * xv.w;
                acc1[s] += w10 * xv.x + w11 * xv.y + w12 * xv.z + w13 * xv.w;
            }
        }
    }
    __syncthreads();

#pragma unroll
    for (int s = 0; s < 16; s++) {
        s_h[s * SH + oc0] = acc0[s];
        s_h[s * SH + oc1] = acc1[s];
    }
    __syncthreads();

    // per-sample ternarize params (16 half-warp groups of 16 lanes)
    {
        int s = tid >> 4, j = tid & 15;
        float sum = 0.f;
        for (int i = j; i < 512; i += 16) sum += fabsf(s_h[s * SH + i]);
#pragma unroll
        for (int o = 8; o > 0; o >>= 1) sum += __shfl_xor_sync(0xffffffffu, sum, o);
        float d = 0.7f * sum / 512.0f;
        float ms = 0.f, c = 0.f;
        for (int i = j; i < 512; i += 16) {
            float a = fabsf(s_h[s * SH + i]);
            if (a > d) { ms += a; c += 1.f; }
        }
#pragma unroll
        for (int o = 8; o > 0; o >>= 1) {
            ms += __shfl_xor_sync(0xffffffffu, ms, o);
            c  += __shfl_xor_sync(0xffffffffu, c, o);
        }
        if (j == 0) { s_ad[s] = d; s_ad[16 + s] = ms / c; }
    }
    __syncthreads();

    // relu(ternarize(h)) in place
    for (int i = tid; i < 8192; i += 256) {
        int s = i >> 9, k = i & 511;
        float v = s_h[s * SH + k];
        float d = s_ad[s], a = s_ad[16 + s];
        float t = (v > d) ? a : ((v < -d) ? -a : 0.f);
        s_h[s * SH + k] = fmaxf(t, 0.f);
    }
    __syncthreads();

    // fc2: 16 samples x 10 outputs
    if (tid < 160) {
        int s = tid / 10, oc = tid - s * 10;
        float acc = b2[oc];
        const float* hp = s_h + s * SH;
        const float* wp = s_w2 + oc * SW2;
#pragma unroll 8
        for (int k = 0; k < 512; k++) acc += hp[k] * wp[k];
        s_o[s * 10 + oc] = acc;
    }
    __syncthreads();

    // final per-sample ternarize over 10 values
    if (tid < 16) {
        int s = tid;
        float v[10];
        float sum = 0.f;
#pragma unroll
        for (int j = 0; j < 10; j++) {
            v[j] = s_o[s * 10 + j];
            sum += fabsf(v[j]);
        }
        float d = 0.7f * sum / 10.0f;
        float ms = 0.f, c = 0.f;
#pragma unroll
        for (int j = 0; j < 10; j++) {
            float a = fabsf(v[j]);
            if (a > d) { ms += a; c += 1.f; }
        }
        float a = ms / c;
        float* op = out + (n0 + s) * 10;
#pragma unroll
        for (int j = 0; j < 10; j++)
            op[j] = (v[j] > d) ? a : ((v[j] < -d) ? -a : 0.f);
    }
}

// ---------------------------------------------------------------------------
extern "C" void kernel_launch(void* const* d_in, const int* in_sizes, int n_in,
                              void* d_out, int out_size) {
    const float* x   = (const float*)d_in[0];
    const float* c1w = (const float*)d_in[1];
    const float* c1b = (const float*)d_in[2];
    const float* g1  = (const float*)d_in[3];
    const float* b1n = (const float*)d_in[4];
    const float* c2w = (const float*)d_in[5];
    const float* c2b = (const float*)d_in[6];
    const float* g2  = (const float*)d_in[7];
    const float* b2n = (const float*)d_in[8];
    const float* w1  = (const float*)d_in[9];
    const float* fb1 = (const float*)d_in[10];
    const float* w2  = (const float*)d_in[11];
    const float* fb2 = (const float*)d_in[12];
    float* out = (float*)d_out;

    const int B = in_sizes[0] / 784;

    const int smem1 = 20076 * 4;   // 80304 B
    const int smem3 = 38586 * 4;   // 154344 B
    cudaFuncSetAttribute(k_conv1, cudaFuncAttributeMaxDynamicSharedMemorySize, smem1);
    cudaFuncSetAttribute(k_fc, cudaFuncAttributeMaxDynamicSharedMemorySize, smem3);

    k_conv1<<<B, 256, smem1>>>(x, c1w, c1b, g1, b1n);
    k_conv2<<<B, 256>>>(c2w, c2b, g2, b2n);
    k_fc<<<B / 16, 256, smem3>>>(w1, fb1, w2, fb2, out);
}

// round 2
// speedup vs baseline: 1.4646x; 1.4646x over previous
#include <cuda_runtime.h>
#include <math.h>

#define BN_INV 0.9999950000374997f

typedef unsigned long long u64;

__device__ __forceinline__ u64 ffma2(u64 a, u64 b, u64 c) {
    u64 d;
    asm("fma.rn.f32x2 %0, %1, %2, %3;" : "=l"(d) : "l"(a), "l"(b), "l"(c));
    return d;
}
__device__ __forceinline__ u64 pack2(float lo, float hi) {
    u64 r;
    asm("mov.b64 %0, {%1, %2};" : "=l"(r) : "f"(lo), "f"(hi));
    return r;
}
__device__ __forceinline__ float2 unpack2(u64 v) {
    float2 f;
    asm("mov.b64 {%0, %1}, %2;" : "=f"(f.x), "=f"(f.y) : "l"(v));
    return f;
}

// Scratch (allocation-free rule -> __device__ globals)
__device__ float  g_h1[2048 * 32 * 12 * 12];   // stage1 out [B,32,12,12]
__device__ float2 g_h2p[1024 * 1024];          // stage2 out, pair-interleaved [B/2][1024]{s0,s1}
__device__ float  g_w1t[1024 * 512];           // fc1 weights transposed [k][oc]

// ---------------------------------------------------------------------------
// Scalar block reduce (256 threads)
// ---------------------------------------------------------------------------
__device__ __forceinline__ float blockReduceSum(float v, volatile float* sred, int tid) {
#pragma unroll
    for (int o = 16; o > 0; o >>= 1) v += __shfl_xor_sync(0xffffffffu, v, o);
    if ((tid & 31) == 0) sred[tid >> 5] = v;
    __syncthreads();
    if (tid < 32) {
        float x = (tid < 8) ? sred[tid] : 0.f;
#pragma unroll
        for (int o = 16; o > 0; o >>= 1) x += __shfl_xor_sync(0xffffffffu, x, o);
        if (tid == 0) sred[0] = x;
    }
    __syncthreads();
    float total = sred[0];
    __syncthreads();
    return total;
}

// Paired block reduce (256 threads = 8 warps); sred must hold >= 16 floats
__device__ __forceinline__ float2 blockReduceSum2(float2 v, volatile float* sred, int tid) {
#pragma unroll
    for (int o = 16; o > 0; o >>= 1) {
        v.x += __shfl_xor_sync(0xffffffffu, v.x, o);
        v.y += __shfl_xor_sync(0xffffffffu, v.y, o);
    }
    if ((tid & 31) == 0) {
        sred[(tid >> 5) * 2]     = v.x;
        sred[(tid >> 5) * 2 + 1] = v.y;
    }
    __syncthreads();
    if (tid < 32) {
        float a = (tid < 8) ? sred[tid * 2] : 0.f;
        float b = (tid < 8) ? sred[tid * 2 + 1] : 0.f;
#pragma unroll
        for (int o = 4; o > 0; o >>= 1) {
            a += __shfl_xor_sync(0xffffffffu, a, o);
            b += __shfl_xor_sync(0xffffffffu, b, o);
        }
        if (tid == 0) { sred[0] = a; sred[1] = b; }
    }
    __syncthreads();
    float2 r = make_float2(sred[0], sred[1]);
    __syncthreads();
    return r;
}

// ---------------------------------------------------------------------------
// Kernel 0: transpose fc1 weights  w1[512][1024] -> g_w1t[1024][512]
// ---------------------------------------------------------------------------
__global__ __launch_bounds__(256) void k_tw1(const float* __restrict__ w1) {
    __shared__ float t[32][33];
    int kb = blockIdx.x * 32;   // k tile (1024/32 = 32 blocks in x)
    int ob = blockIdx.y * 32;   // oc tile (512/32 = 16 blocks in y)
    int lx = threadIdx.x & 31, ly = threadIdx.x >> 5;
#pragma unroll
    for (int r = ly; r < 32; r += 8) t[r][lx] = w1[(ob + r) * 1024 + kb + lx];
    __syncthreads();
#pragma unroll
    for (int r = ly; r < 32; r += 8) g_w1t[(kb + r) * 512 + ob + lx] = t[lx][r];
}

// ---------------------------------------------------------------------------
// Kernel 1: conv1(1->32, 5x5, 28->24) + tern + BN + maxpool2 + relu -> g_h1
// (unchanged from round 1)
// ---------------------------------------------------------------------------
__global__ __launch_bounds__(256) void k_conv1(
    const float* __restrict__ x, const float* __restrict__ w,
    const float* __restrict__ bconv, const float* __restrict__ bng,
    const float* __restrict__ bnb) {
    extern __shared__ float sm[];
    float* s_in   = sm;          // 28 * 29 = 812
    float* s_w    = sm + 812;    // 800
    float* s_b    = sm + 1612;   // 32
    float* s_conv = sm + 1644;   // 18432
    __shared__ float sred[32];

    const int n = blockIdx.x;
    const int tid = threadIdx.x;

    const float* xin = x + n * 784;
    for (int i = tid; i < 784; i += 256) {
        int r = i / 28, c = i - r * 28;
        s_in[r * 29 + c] = xin[i];
    }
    for (int i = tid; i < 800; i += 256) s_w[i] = w[i];
    if (tid < 32) s_b[tid] = bconv[tid];
    __syncthreads();

    float labs = 0.f;
#pragma unroll
    for (int p = 0; p < 3; p++) {
        int pair = tid + p * 256;
        int oc = pair / 24, oy = pair - oc * 24;
        float acc[24];
        float bias = s_b[oc];
#pragma unroll
        for (int ox = 0; ox < 24; ox++) acc[ox] = bias;
#pragma unroll
        for (int kh = 0; kh < 5; kh++) {
            float row[28];
            const float* rp = s_in + (oy + kh) * 29;
#pragma unroll
            for (int j = 0; j < 28; j++) row[j] = rp[j];
            const float* wp = s_w + oc * 25 + kh * 5;
#pragma unroll
            for (int kw = 0; kw < 5; kw++) {
                float wv = wp[kw];
#pragma unroll
                for (int ox = 0; ox < 24; ox++) acc[ox] += wv * row[ox + kw];
            }
        }
        float* cp = s_conv + oc * 576 + oy * 24;
#pragma unroll
        for (int ox = 0; ox < 24; ox++) {
            cp[ox] = acc[ox];
            labs += fabsf(acc[ox]);
        }
    }

    float total = blockReduceSum(labs, sred, tid);
    float delta = 0.7f * total / 18432.0f;

    float msum = 0.f, cnt = 0.f;
    for (int i = tid; i < 18432; i += 256) {
        float a = fabsf(s_conv[i]);
        if (a > delta) { msum += a; cnt += 1.f; }
    }
    msum = blockReduceSum(msum, sred, tid);
    cnt  = blockReduceSum(cnt, sred, tid);
    float alpha = msum / cnt;

    float* outp = g_h1 + n * 4608;
    for (int p = tid; p < 4608; p += 256) {
        int c = p / 144;
        int r = p - c * 144;
        int py = r / 12, px = r - py * 12;
        float sc = bng[c] * BN_INV, sh = bnb[c];
        const float* base = s_conv + c * 576 + (py * 2) * 24 + px * 2;
        float m = -1e30f;
#pragma unroll
        for (int dy = 0; dy < 2; dy++)
#pragma unroll
            for (int dx = 0; dx < 2; dx++) {
                float v = base[dy * 24 + dx];
                float t = (v > delta) ? alpha : ((v < -delta) ? -alpha : 0.f);
                float bnv = t * sc + sh;
                m = fmaxf(m, bnv);
            }
        outp[p] = fmaxf(m, 0.f);
    }
}

// ---------------------------------------------------------------------------
// Kernel 2: conv2(32->64, 5x5, 12->8) + tern + BN + maxpool2 + relu
// 2 SAMPLES per CTA packed in f32x2 lanes. 256 threads = 64 oc * 4 row-pairs.
// s_in2 rows padded to 13 float2 (conflict-free). Writes g_h2p pair-interleaved.
// ---------------------------------------------------------------------------
__global__ __launch_bounds__(256) void k_conv2(
    const float* __restrict__ w, const float* __restrict__ bconv,
    const float* __restrict__ bng, const float* __restrict__ bnb) {
    extern __shared__ float smraw[];
    float2* s_in2   = (float2*)smraw;                 // 32 * 12 * 13 = 4992 float2
    float2* s_conv2 = (float2*)(smraw + 4992 * 2);    // 4096 float2
    __shared__ float sred[16];

    const int n2 = blockIdx.x;      // sample pair index
    const int tid = threadIdx.x;

    const float* x0 = g_h1 + (2 * n2) * 4608;
    const float* x1 = g_h1 + (2 * n2 + 1) * 4608;
    for (int i = tid; i < 4608; i += 256) {
        int ic = i / 144;
        int r  = i - ic * 144;
        int rr = r / 12, c = r - rr * 12;
        s_in2[ic * 156 + rr * 13 + c] = make_float2(x0[i], x1[i]);
    }
    __syncthreads();

    const int oc = tid >> 2;        // 0..63
    const int q  = tid & 3;
    const int y0 = q * 2;           // output rows y0, y0+1

    u64 acc0[8], acc1[8];
    {
        float b = bconv[oc];
        u64 bb = pack2(b, b);
#pragma unroll
        for (int i = 0; i < 8; i++) { acc0[i] = bb; acc1[i] = bb; }
    }

    for (int ic = 0; ic < 32; ic++) {
        const float* wb = w + (oc * 32 + ic) * 25;
        float wv[25];
#pragma unroll
        for (int i = 0; i < 25; i++) wv[i] = __ldg(wb + i);
        const float2* ib = s_in2 + ic * 156;
#pragma unroll
        for (int rr = 0; rr < 6; rr++) {
            u64 row[12];
            const u64* rp = (const u64*)(ib + (y0 + rr) * 13);
#pragma unroll
            for (int j = 0; j < 12; j++) row[j] = rp[j];
            if (rr < 5) {
#pragma unroll
                for (int kw = 0; kw < 5; kw++) {
                    float s = wv[rr * 5 + kw];
                    u64 wd = pack2(s, s);
#pragma unroll
                    for (int ox = 0; ox < 8; ox++)
                        acc0[ox] = ffma2(wd, row[ox + kw], acc0[ox]);
                }
            }
            if (rr >= 1) {
#pragma unroll
                for (int kw = 0; kw < 5; kw++) {
                    float s = wv[(rr - 1) * 5 + kw];
                    u64 wd = pack2(s, s);
#pragma unroll
                    for (int ox = 0; ox < 8; ox++)
                        acc1[ox] = ffma2(wd, row[ox + kw], acc1[ox]);
                }
            }
        }
    }

    // stash conv outputs (packed) + per-lane |.| sums
    float2 labs = make_float2(0.f, 0.f);
#pragma unroll
    for (int ox = 0; ox < 8; ox++) {
        float2 v0 = unpack2(acc0[ox]);
        float2 v1 = unpack2(acc1[ox]);
        s_conv2[oc * 64 + y0 * 8 + ox]       = v0;
        s_conv2[oc * 64 + (y0 + 1) * 8 + ox] = v1;
        labs.x += fabsf(v0.x) + fabsf(v1.x);
        labs.y += fabsf(v0.y) + fabsf(v1.y);
    }

    float2 tot = blockReduceSum2(labs, sred, tid);
    float d0 = 0.7f * tot.x / 4096.0f;
    float d1 = 0.7f * tot.y / 4096.0f;

    float2 ms = make_float2(0.f, 0.f), cn = make_float2(0.f, 0.f);
#pragma unroll
    for (int ox = 0; ox < 8; ox++) {
        float2 v0 = unpack2(acc0[ox]);
        float2 v1 = unpack2(acc1[ox]);
        float a;
        a = fabsf(v0.x); if (a > d0) { ms.x += a; cn.x += 1.f; }
        a = fabsf(v1.x); if (a > d0) { ms.x += a; cn.x += 1.f; }
        a = fabsf(v0.y); if (a > d1) { ms.y += a; cn.y += 1.f; }
        a = fabsf(v1.y); if (a > d1) { ms.y += a; cn.y += 1.f; }
    }
    ms = blockReduceSum2(ms, sred, tid);
    cn = blockReduceSum2(cn, sred, tid);
    float a0v = ms.x / cn.x;
    float a1v = ms.y / cn.y;

    // tern -> BN -> maxpool2 -> relu, write pair-interleaved
    float2* outp = g_h2p + n2 * 1024;
    for (int p = tid; p < 1024; p += 256) {
        int c = p >> 4;
        int r = p & 15;
        int py = r >> 2, px = r & 3;
        float sc = bng[c] * BN_INV, sh = bnb[c];
        const float2* base = s_conv2 + c * 64 + (py * 2) * 8 + px * 2;
        float m0 = -1e30f, m1 = -1e30f;
#pragma unroll
        for (int dy = 0; dy < 2; dy++)
#pragma unroll
            for (int dx = 0; dx < 2; dx++) {
                float2 v = base[dy * 8 + dx];
                float t0 = (v.x > d0) ? a0v : ((v.x < -d0) ? -a0v : 0.f);
                float t1 = (v.y > d1) ? a1v : ((v.y < -d1) ? -a1v : 0.f);
                m0 = fmaxf(m0, t0 * sc + sh);
                m1 = fmaxf(m1, t1 * sc + sh);
            }
        outp[p] = make_float2(fmaxf(m0, 0.f), fmaxf(m1, 0.f));
    }
}

// ---------------------------------------------------------------------------
// Kernel 3: fc1 (1024->512) + tern + relu + fc2 (512->10) + tern -> out
// 16 samples (8 pairs) per CTA, pairs packed in f32x2 lanes.
// Weights from g_w1t (coalesced LDG), x from smem (uniform broadcast).
// ---------------------------------------------------------------------------
#define SH 516

__global__ __launch_bounds__(256) void k_fc(
    const float* __restrict__ b1, const float* __restrict__ w2,
    const float* __restrict__ b2, float* __restrict__ out) {
    extern __shared__ float sm[];
    float2* s_x2 = (float2*)sm;              // 8 * 1024 float2 = 65536 B
    float*  s_h  = sm + 16384;               // 16 * SH = 8256 floats
    float*  s_o  = s_h + 16 * SH;            // 160
    float*  s_ad = s_o + 160;                // 32

    const int tid = threadIdx.x;
    const int pr0 = blockIdx.x * 8;          // first sample pair
    const int n0  = blockIdx.x * 16;         // first sample

    for (int i = tid; i < 8192; i += 256) s_x2[i] = g_h2p[pr0 * 1024 + i];
    __syncthreads();

    const int oc0 = tid, oc1 = tid + 256;
    u64 a0[8], a1[8];
    {
        float bA = b1[oc0], bB = b1[oc1];
        u64 pA = pack2(bA, bA), pB = pack2(bB, bB);
#pragma unroll
        for (int p = 0; p < 8; p++) { a0[p] = pA; a1[p] = pB; }
    }

#pragma unroll 2
    for (int kt = 0; kt < 1024; kt += 4) {
        float wa0 = __ldg(&g_w1t[(kt + 0) * 512 + oc0]);
        float wa1 = __ldg(&g_w1t[(kt + 1) * 512 + oc0]);
        float wa2 = __ldg(&g_w1t[(kt + 2) * 512 + oc0]);
        float wa3 = __ldg(&g_w1t[(kt + 3) * 512 + oc0]);
        float wb0 = __ldg(&g_w1t[(kt + 0) * 512 + oc1]);
        float wb1 = __ldg(&g_w1t[(kt + 1) * 512 + oc1]);
        float wb2 = __ldg(&g_w1t[(kt + 2) * 512 + oc1]);
        float wb3 = __ldg(&g_w1t[(kt + 3) * 512 + oc1]);
        u64 WA0 = pack2(wa0, wa0), WA1 = pack2(wa1, wa1);
        u64 WA2 = pack2(wa2, wa2), WA3 = pack2(wa3, wa3);
        u64 WB0 = pack2(wb0, wb0), WB1 = pack2(wb1, wb1);
        u64 WB2 = pack2(wb2, wb2), WB3 = pack2(wb3, wb3);
#pragma unroll
        for (int p = 0; p < 8; p++) {
            const ulonglong2* xp = (const ulonglong2*)(s_x2 + p * 1024 + kt);
            ulonglong2 xa = xp[0];
            ulonglong2 xb = xp[1];
            a0[p] = ffma2(WA0, xa.x, a0[p]);
            a0[p] = ffma2(WA1, xa.y, a0[p]);
            a0[p] = ffma2(WA2, xb.x, a0[p]);
            a0[p] = ffma2(WA3, xb.y, a0[p]);
            a1[p] = ffma2(WB0, xa.x, a1[p]);
            a1[p] = ffma2(WB1, xa.y, a1[p]);
            a1[p] = ffma2(WB2, xb.x, a1[p]);
            a1[p] = ffma2(WB3, xb.y, a1[p]);
        }
    }
    __syncthreads();

#pragma unroll
    for (int p = 0; p < 8; p++) {
        float2 v0 = unpack2(a0[p]);
        float2 v1 = unpack2(a1[p]);
        s_h[(2 * p) * SH + oc0]     = v0.x;
        s_h[(2 * p + 1) * SH + oc0] = v0.y;
        s_h[(2 * p) * SH + oc1]     = v1.x;
        s_h[(2 * p + 1) * SH + oc1] = v1.y;
    }
    __syncthreads();

    // per-sample ternarize params (16 groups of 16 lanes)
    {
        int s = tid >> 4, j = tid & 15;
        float sum = 0.f;
        for (int i = j; i < 512; i += 16) sum += fabsf(s_h[s * SH + i]);
#pragma unroll
        for (int o = 8; o > 0; o >>= 1) sum += __shfl_xor_sync(0xffffffffu, sum, o);
        float d = 0.7f * sum / 512.0f;
        float msv = 0.f, c = 0.f;
        for (int i = j; i < 512; i += 16) {
            float a = fabsf(s_h[s * SH + i]);
            if (a > d) { msv += a; c += 1.f; }
        }
#pragma unroll
        for (int o = 8; o > 0; o >>= 1) {
            msv += __shfl_xor_sync(0xffffffffu, msv, o);
            c   += __shfl_xor_sync(0xffffffffu, c, o);
        }
        if (j == 0) { s_ad[s] = d; s_ad[16 + s] = msv / c; }
    }
    __syncthreads();

    // relu(ternarize(h)) in place
    for (int i = tid; i < 8192; i += 256) {
        int s = i >> 9, k = i & 511;
        float v = s_h[s * SH + k];
        float d = s_ad[s], a = s_ad[16 + s];
        float t = (v > d) ? a : ((v < -d) ? -a : 0.f);
        s_h[s * SH + k] = fmaxf(t, 0.f);
    }
    __syncthreads();

    // fc2: 16 samples x 10 outputs
    if (tid < 160) {
        int s = tid / 10, oc = tid - s * 10;
        float acc = b2[oc];
        const float* hp = s_h + s * SH;
        const float* wp = w2 + oc * 512;
#pragma unroll 4
        for (int k = 0; k < 512; k += 4) {
            float4 wv4 = *(const float4*)(wp + k);
            float4 hv4 = *(const float4*)(hp + k);
            acc += hv4.x * wv4.x + hv4.y * wv4.y + hv4.z * wv4.z + hv4.w * wv4.w;
        }
        s_o[s * 10 + oc] = acc;
    }
    __syncthreads();

    // final per-sample ternarize over 10 values
    if (tid < 16) {
        int s = tid;
        float v[10];
        float sum = 0.f;
#pragma unroll
        for (int j = 0; j < 10; j++) {
            v[j] = s_o[s * 10 + j];
            sum += fabsf(v[j]);
        }
        float d = 0.7f * sum / 10.0f;
        float msv = 0.f, c = 0.f;
#pragma unroll
        for (int j = 0; j < 10; j++) {
            float a = fabsf(v[j]);
            if (a > d) { msv += a; c += 1.f; }
        }
        float a = msv / c;
        float* op = out + (n0 + s) * 10;
#pragma unroll
        for (int j = 0; j < 10; j++)
            op[j] = (v[j] > d) ? a : ((v[j] < -d) ? -a : 0.f);
    }
}

// ---------------------------------------------------------------------------
extern "C" void kernel_launch(void* const* d_in, const int* in_sizes, int n_in,
                              void* d_out, int out_size) {
    const float* x   = (const float*)d_in[0];
    const float* c1w = (const float*)d_in[1];
    const float* c1b = (const float*)d_in[2];
    const float* g1  = (const float*)d_in[3];
    const float* b1n = (const float*)d_in[4];
    const float* c2w = (const float*)d_in[5];
    const float* c2b = (const float*)d_in[6];
    const float* g2  = (const float*)d_in[7];
    const float* b2n = (const float*)d_in[8];
    const float* w1  = (const float*)d_in[9];
    const float* fb1 = (const float*)d_in[10];
    const float* w2  = (const float*)d_in[11];
    const float* fb2 = (const float*)d_in[12];
    float* out = (float*)d_out;

    const int B = in_sizes[0] / 784;

    const int smem1 = 20076 * 4;               // 80304 B
    const int smem2 = (4992 + 4096) * 8;       // 72704 B
    const int smem3 = (16384 * 2 + 16 * SH + 160 + 32) * 4;  // 99328 B... (see note)
    // s_x2 is 8192 float2 = 16384 floats; layout above uses sm + 16384 floats.
    cudaFuncSetAttribute(k_conv1, cudaFuncAttributeMaxDynamicSharedMemorySize, smem1);
    cudaFuncSetAttribute(k_conv2, cudaFuncAttributeMaxDynamicSharedMemorySize, smem2);
    cudaFuncSetAttribute(k_fc,    cudaFuncAttributeMaxDynamicSharedMemorySize, smem3);

    k_tw1<<<dim3(32, 16), 256>>>(w1);
    k_conv1<<<B, 256, smem1>>>(x, c1w, c1b, g1, b1n);
    k_conv2<<<B / 2, 256, smem2>>>(c2w, c2b, g2, b2n);
    k_fc<<<B / 16, 256, smem3>>>(fb1, w2, fb2, out);
}